// round 8
// baseline (speedup 1.0000x reference)
#include <cuda_runtime.h>
#include <cstdint>

#define Bsz  16384
#define Gn   128
#define Sn   64
#define Hn   10
#define PHn  100

typedef unsigned long long ull;

// scratch: gene_layer stored transposed [G][B]
__device__ float g_GL[(size_t)Gn * Bsz];

// ---------------- packed f32x2 helpers (sm_103a) ----------------
__device__ __forceinline__ ull ffma2(ull a, ull b, ull c) {
    ull d;
    asm("fma.rn.f32x2 %0, %1, %2, %3;" : "=l"(d) : "l"(a), "l"(b), "l"(c));
    return d;
}
__device__ __forceinline__ ull add2(ull a, ull b) {
    ull d;
    asm("add.rn.f32x2 %0, %1, %2;" : "=l"(d) : "l"(a), "l"(b));
    return d;
}
__device__ __forceinline__ ull dup2(float x) {
    ull r;
    asm("mov.b64 %0, {%1, %1};" : "=l"(r) : "f"(x));
    return r;
}
__device__ __forceinline__ void unpack2(ull v, float& lo, float& hi) {
    asm("mov.b64 {%0, %1}, %2;" : "=f"(lo), "=f"(hi) : "l"(v));
}

// ---------------- cp.async helpers ----------------
__device__ __forceinline__ void cpa16(uint32_t dst, const float4* src) {
    asm volatile("cp.async.cg.shared.global [%0], [%1], 16;"
                 :: "r"(dst), "l"(src));
}
__device__ __forceinline__ void cpa_commit() {
    asm volatile("cp.async.commit_group;");
}
__device__ __forceinline__ void cpa_wait2() {
    asm volatile("cp.async.wait_group 2;");
}

// =======================================================================
// Stage 1: per-gene MLP.  4 lanes per row (16 SNPs each), 2 rows/thread.
//   cp.async 3-stage pipeline; each thread prefetches exactly the smem it
//   consumes -> no __syncthreads in the hot loop.
//   grid = (G, B/ROWS1), block = 128
// =======================================================================
#define TH1      128
#define ROWS1    512
#define PASS1    8
#define XS_STAGE 4352              // 64 rows * 68 floats per stage
#define SMEM1_BYTES (2736 + 3 * XS_STAGE * 4)   // 54960

__global__ void __launch_bounds__(TH1)
stage1_kernel(const float* __restrict__ x,
              const float* __restrict__ W1,
              const float* __restrict__ b1,
              const float* __restrict__ W2,
              const float* __restrict__ b2)
{
    extern __shared__ char smraw[];
    ull*   ws  = reinterpret_cast<ull*>(smraw);          // 336 ull (2688 B)
    float* w2s = reinterpret_cast<float*>(smraw + 2688); // 12 floats
    float* xs  = reinterpret_cast<float*>(smraw + 2736); // [3][64][68]

    const int g   = blockIdx.x;
    const int tid = threadIdx.x;

    // ---- stage W1 pairs slice-major (padded) ----
    const ull* W1u = reinterpret_cast<const ull*>(W1 + (size_t)g * Sn * Hn);
    for (int p = tid; p < Sn * (Hn / 2); p += TH1) {   // 320 pairs
        int s = p / 5, hp = p % 5;
        int j = (s >> 2) & 3;
        int k = s >> 4;
        int i = s & 3;
        ws[j * 82 + (k * 4 + i) * 5 + hp] = W1u[p];
    }
    if (tid < 5)  ws[328 + tid] = reinterpret_cast<const ull*>(b1 + g * Hn)[tid];
    if (tid < 10) w2s[tid] = W2[g * Hn + tid];
    if (tid == 0) w2s[10] = b2[g];
    __syncthreads();

    const int w    = tid >> 5;
    const int lane = tid & 31;
    const int rg   = lane >> 2;      // 0..7
    const int j2   = lane & 3;       // slice
    const ull* wsl = ws + j2 * 82;

    ull b1r[5];
#pragma unroll
    for (int hp = 0; hp < 5; hp++) b1r[hp] = ws[328 + hp];
    float w2r[10];
#pragma unroll
    for (int h = 0; h < 10; h++) w2r[h] = w2s[h];
    const float b2v = w2s[10];

    // per-thread smem byte offset within a stage
    const uint32_t xs_sa = (uint32_t)__cvta_generic_to_shared(xs);
    const uint32_t toff  = (uint32_t)(((w * 16 + rg) * 68 + 4 * j2) * 4);

    const float4* x4 = reinterpret_cast<const float4*>(x);
    // float4 index of (row, g, chunk k, slice j2) = row*2048 + g*16 + 4k + j2
    const size_t gidx = (size_t)(blockIdx.y * ROWS1 + w * 16 + rg) * 2048
                        + (size_t)g * 16 + j2;

    // ---- prologue: prefetch stages 0..2 ----
#pragma unroll
    for (int s = 0; s < 3; s++) {
        uint32_t d = xs_sa + (uint32_t)s * (XS_STAGE * 4) + toff;
        const float4* sp = x4 + gidx + (size_t)s * 131072;
#pragma unroll
        for (int k = 0; k < 4; k++) {
            cpa16(d + k * 64,        sp + k * 4);
            cpa16(d + 2176 + k * 64, sp + 16384 + k * 4);
        }
        cpa_commit();
    }

    int buf = 0;
    int rA  = blockIdx.y * ROWS1 + w * 16 + rg;

#pragma unroll 1
    for (int pass = 0; pass < PASS1; pass++) {
        cpa_wait2();   // stage `pass` complete (2 newer groups may be pending)

        // load this pass's 8 float4 from smem into registers
        const float4* c4 = reinterpret_cast<const float4*>(
            xs + buf * XS_STAGE + (w * 16 + rg) * 68 + 4 * j2);
        float4 xa[4], xb[4];
#pragma unroll
        for (int k = 0; k < 4; k++) {
            xa[k] = c4[k * 4];
            xb[k] = c4[136 + k * 4];
        }

        // immediately refill this buffer for stage pass+3 (after the LDS above;
        // cp.async data arrival is ~600cyc after the 29cyc LDS -> safe)
        if (pass + 3 < PASS1) {
            uint32_t d = xs_sa + (uint32_t)buf * (XS_STAGE * 4) + toff;
            const float4* sp = x4 + gidx + (size_t)(pass + 3) * 131072;
#pragma unroll
            for (int k = 0; k < 4; k++) {
                cpa16(d + k * 64,        sp + k * 4);
                cpa16(d + 2176 + k * 64, sp + 16384 + k * 4);
            }
        }
        cpa_commit();   // always commit (possibly empty) to keep group count uniform

        // ---- math ----
        ull accA[5], accB[5];
#pragma unroll
        for (int hp = 0; hp < 5; hp++) { accA[hp] = 0ull; accB[hp] = 0ull; }

#pragma unroll
        for (int k = 0; k < 4; k++) {
            float fa[4] = {xa[k].x, xa[k].y, xa[k].z, xa[k].w};
            float fb[4] = {xb[k].x, xb[k].y, xb[k].z, xb[k].w};
#pragma unroll
            for (int i = 0; i < 4; i++) {
                ull a2 = dup2(fa[i]);
                ull c2 = dup2(fb[i]);
                const ull* wrow = wsl + (k * 4 + i) * 5;
#pragma unroll
                for (int hp = 0; hp < 5; hp++) {
                    ull wv = wrow[hp];
                    accA[hp] = ffma2(a2, wv, accA[hp]);
                    accB[hp] = ffma2(c2, wv, accB[hp]);
                }
            }
        }

#pragma unroll
        for (int off = 1; off <= 2; off <<= 1) {
#pragma unroll
            for (int hp = 0; hp < 5; hp++) {
                accA[hp] = add2(accA[hp], __shfl_xor_sync(0xffffffffu, accA[hp], off));
                accB[hp] = add2(accB[hp], __shfl_xor_sync(0xffffffffu, accB[hp], off));
            }
        }

        float glA = b2v, glB = b2v;
#pragma unroll
        for (int hp = 0; hp < 5; hp++) {
            float l, h;
            unpack2(add2(accA[hp], b1r[hp]), l, h);
            glA += fmaxf(l, 0.f) * w2r[2 * hp] + fmaxf(h, 0.f) * w2r[2 * hp + 1];
            unpack2(add2(accB[hp], b1r[hp]), l, h);
            glB += fmaxf(l, 0.f) * w2r[2 * hp] + fmaxf(h, 0.f) * w2r[2 * hp + 1];
        }
        if (j2 == 0) {
            g_GL[(size_t)g * Bsz + rA]     = glA;
            g_GL[(size_t)g * Bsz + rA + 8] = glB;
        }
        rA += 64;
        buf = (buf == 2) ? 0 : buf + 1;
    }
}

// =======================================================================
// Stage 2: 8 threads per batch row: (PH half) x (G quarter).
//   lane: bits[0:2)=row(4), bits[2:4)=gh quarter, bit4=ph half.
//   grid = B/16 = 1024 CTAs, block = 128 (16 rows/CTA)
// =======================================================================
#define TH2   128
#define WR    104
#define SMEM2_BYTES (13328 * 4)

__global__ void __launch_bounds__(TH2)
stage2_kernel(const float* __restrict__ Wp1,
              const float* __restrict__ bp1,
              const float* __restrict__ Wp2,
              const float* __restrict__ bp2,
              float* __restrict__ out)
{
    extern __shared__ float wp[];
    // layout: gene gg row at  gg*104 + (gg>>5)*4 ; half0 cols 0..49, half1 cols 52..101
    const int tid  = threadIdx.x;
    const int lane = tid & 31;
    const int wrp  = tid >> 5;

    for (int i = tid; i < Gn * PHn; i += TH2) {
        int gg = i / PHn, p = i - gg * PHn;
        int col = (p < 50) ? p : p + 2;
        wp[gg * WR + (gg >> 5) * 4 + col] = Wp1[i];
    }
    __syncthreads();

    const int row = lane & 3;
    const int gh  = (lane >> 2) & 3;
    const int ph  = lane >> 4;
    const int b   = blockIdx.x * 16 + wrp * 4 + row;

    ull acc[25];
    if (gh == 0) {
        const ull* s = reinterpret_cast<const ull*>(bp1 + ph * 50);
#pragma unroll
        for (int q = 0; q < 25; q++) acc[q] = s[q];
    } else {
#pragma unroll
        for (int q = 0; q < 25; q++) acc[q] = 0ull;
    }

    const float* glp = g_GL + (size_t)(gh * 32) * Bsz + b;
    const float* wr0 = wp + (gh * 32) * WR + gh * 4 + ph * 52;

#pragma unroll 1
    for (int c = 0; c < 32; c += 8) {
        float gv[8];
#pragma unroll
        for (int j = 0; j < 8; j++) gv[j] = glp[(size_t)(c + j) * Bsz];
        const float* wr = wr0 + c * WR;
#pragma unroll
        for (int j = 0; j < 8; j++) {
            ull a2 = dup2(gv[j]);
            const ulonglong2* w2p = reinterpret_cast<const ulonglong2*>(wr);
#pragma unroll
            for (int q = 0; q < 12; q++) {
                ulonglong2 wv = w2p[q];
                acc[2 * q]     = ffma2(a2, wv.x, acc[2 * q]);
                acc[2 * q + 1] = ffma2(a2, wv.y, acc[2 * q + 1]);
            }
            acc[24] = ffma2(a2, reinterpret_cast<const ull*>(wr)[24], acc[24]);
            wr += WR;
        }
    }

    // combine G quarters (gh bits 2,3)
#pragma unroll
    for (int off = 4; off <= 8; off <<= 1) {
#pragma unroll
        for (int q = 0; q < 25; q++)
            acc[q] = add2(acc[q], __shfl_xor_sync(0xffffffffu, acc[q], off));
    }

    // relu + dot with own Wp2 half
    float y = 0.f;
    const ull* wp2u = reinterpret_cast<const ull*>(Wp2 + ph * 50);
#pragma unroll
    for (int q = 0; q < 25; q++) {
        float l, h, wl, wh;
        unpack2(acc[q], l, h);
        unpack2(wp2u[q], wl, wh);
        y += fmaxf(l, 0.f) * wl + fmaxf(h, 0.f) * wh;
    }
    // combine PH halves (bit 4)
    y += __shfl_xor_sync(0xffffffffu, y, 16);

    if ((lane >> 2) == 0) out[b] = y + bp2[0];
}

// =======================================================================
extern "C" void kernel_launch(void* const* d_in, const int* in_sizes, int n_in,
                              void* d_out, int out_size)
{
    const float* x   = (const float*)d_in[0];
    const float* W1  = (const float*)d_in[1];
    const float* b1  = (const float*)d_in[2];
    const float* W2  = (const float*)d_in[3];
    const float* b2  = (const float*)d_in[4];
    const float* Wp1 = (const float*)d_in[5];
    const float* bp1 = (const float*)d_in[6];
    const float* Wp2 = (const float*)d_in[7];
    const float* bp2 = (const float*)d_in[8];
    float* out = (float*)d_out;

    cudaFuncSetAttribute(stage1_kernel,
                         cudaFuncAttributeMaxDynamicSharedMemorySize, SMEM1_BYTES);
    cudaFuncSetAttribute(stage2_kernel,
                         cudaFuncAttributeMaxDynamicSharedMemorySize, SMEM2_BYTES);

    dim3 grid1(Gn, Bsz / ROWS1);
    stage1_kernel<<<grid1, TH1, SMEM1_BYTES>>>(x, W1, b1, W2, b2);
    stage2_kernel<<<Bsz / 16, TH2, SMEM2_BYTES>>>(Wp1, bp1, Wp2, bp2, out);
}

// round 11
// speedup vs baseline: 1.1024x; 1.1024x over previous
#include <cuda_runtime.h>
#include <cstdint>

#define Bsz  16384
#define Gn   128
#define Sn   64
#define Hn   10
#define PHn  100

typedef unsigned long long ull;

// scratch: gene_layer stored transposed [G][B]
__device__ float g_GL[(size_t)Gn * Bsz];

// ---------------- packed f32x2 helpers (sm_103a) ----------------
__device__ __forceinline__ ull ffma2(ull a, ull b, ull c) {
    ull d;
    asm("fma.rn.f32x2 %0, %1, %2, %3;" : "=l"(d) : "l"(a), "l"(b), "l"(c));
    return d;
}
__device__ __forceinline__ ull add2(ull a, ull b) {
    ull d;
    asm("add.rn.f32x2 %0, %1, %2;" : "=l"(d) : "l"(a), "l"(b));
    return d;
}
__device__ __forceinline__ ull dup2(float x) {
    ull r;
    asm("mov.b64 %0, {%1, %1};" : "=l"(r) : "f"(x));
    return r;
}
__device__ __forceinline__ void unpack2(ull v, float& lo, float& hi) {
    asm("mov.b64 {%0, %1}, %2;" : "=f"(lo), "=f"(hi) : "l"(v));
}

// =======================================================================
// Stage 1 (unchanged from R7 best): per-gene MLP, 4 lanes/row, 2 rows/thread,
//   register double-buffered x loads across 8 passes.
//   grid = (G, B/ROWS1), block = 128
// =======================================================================
#define TH1     128
#define ROWS1   512
#define PASS1   8

__global__ void __launch_bounds__(TH1)
stage1_kernel(const float* __restrict__ x,
              const float* __restrict__ W1,
              const float* __restrict__ b1,
              const float* __restrict__ W2,
              const float* __restrict__ b2)
{
    __shared__ ull  ws[4 * 82 + 8];
    __shared__ float w2s[10];
    __shared__ float b2s;

    const int g   = blockIdx.x;
    const int tid = threadIdx.x;

    const ull* W1u = reinterpret_cast<const ull*>(W1 + (size_t)g * Sn * Hn);
    for (int p = tid; p < Sn * (Hn / 2); p += TH1) {
        int s = p / 5, hp = p % 5;
        int j = (s >> 2) & 3;
        int k = s >> 4;
        int i = s & 3;
        ws[j * 82 + (k * 4 + i) * 5 + hp] = W1u[p];
    }
    if (tid < 5)  ws[4 * 82 + tid] = reinterpret_cast<const ull*>(b1 + g * Hn)[tid];
    if (tid < 10) w2s[tid] = W2[g * Hn + tid];
    if (tid == 0) b2s = b2[g];
    __syncthreads();

    const int w    = tid >> 5;
    const int lane = tid & 31;
    const int rg   = lane >> 2;
    const int j2   = lane & 3;
    const ull* wsl = ws + j2 * 82;

    ull b1r[5];
#pragma unroll
    for (int hp = 0; hp < 5; hp++) b1r[hp] = ws[4 * 82 + hp];
    float w2r[10];
#pragma unroll
    for (int h = 0; h < 10; h++) w2r[h] = w2s[h];
    const float b2v = b2s;

    const int rowbase = blockIdx.y * ROWS1 + w * 16 + rg;
    const float4* x4 = reinterpret_cast<const float4*>(x);

    float4 ca[4], cb[4];
    {
        const size_t iA = (size_t)rowbase * 2048 + (size_t)g * 16 + j2;
#pragma unroll
        for (int k = 0; k < 4; k++) {
            ca[k] = x4[iA + k * 4];
            cb[k] = x4[iA + 8 * 2048 + k * 4];
        }
    }

#pragma unroll 1
    for (int pass = 0; pass < PASS1; pass++) {
        float4 na[4], nb[4];
        if (pass + 1 < PASS1) {
            const size_t iN = (size_t)(rowbase + (pass + 1) * 64) * 2048
                              + (size_t)g * 16 + j2;
#pragma unroll
            for (int k = 0; k < 4; k++) {
                na[k] = x4[iN + k * 4];
                nb[k] = x4[iN + 8 * 2048 + k * 4];
            }
        }

        ull accA[5], accB[5];
#pragma unroll
        for (int hp = 0; hp < 5; hp++) { accA[hp] = 0ull; accB[hp] = 0ull; }

#pragma unroll
        for (int k = 0; k < 4; k++) {
            float fa[4] = {ca[k].x, ca[k].y, ca[k].z, ca[k].w};
            float fb[4] = {cb[k].x, cb[k].y, cb[k].z, cb[k].w};
#pragma unroll
            for (int i = 0; i < 4; i++) {
                ull a2 = dup2(fa[i]);
                ull c2 = dup2(fb[i]);
                const ull* wrow = wsl + (k * 4 + i) * 5;
#pragma unroll
                for (int hp = 0; hp < 5; hp++) {
                    ull wv = wrow[hp];
                    accA[hp] = ffma2(a2, wv, accA[hp]);
                    accB[hp] = ffma2(c2, wv, accB[hp]);
                }
            }
        }

#pragma unroll
        for (int off = 1; off <= 2; off <<= 1) {
#pragma unroll
            for (int hp = 0; hp < 5; hp++) {
                accA[hp] = add2(accA[hp], __shfl_xor_sync(0xffffffffu, accA[hp], off));
                accB[hp] = add2(accB[hp], __shfl_xor_sync(0xffffffffu, accB[hp], off));
            }
        }

        float glA = b2v, glB = b2v;
#pragma unroll
        for (int hp = 0; hp < 5; hp++) {
            float l, h;
            unpack2(add2(accA[hp], b1r[hp]), l, h);
            glA += fmaxf(l, 0.f) * w2r[2 * hp] + fmaxf(h, 0.f) * w2r[2 * hp + 1];
            unpack2(add2(accB[hp], b1r[hp]), l, h);
            glB += fmaxf(l, 0.f) * w2r[2 * hp] + fmaxf(h, 0.f) * w2r[2 * hp + 1];
        }
        const int rA = rowbase + pass * 64;
        if (j2 == 0) {
            g_GL[(size_t)g * Bsz + rA]     = glA;
            g_GL[(size_t)g * Bsz + rA + 8] = glB;
        }

#pragma unroll
        for (int k = 0; k < 4; k++) { ca[k] = na[k]; cb[k] = nb[k]; }
    }
}

// =======================================================================
// Stage 2: register-tiled GEMM [B x G] @ [G x PH], thread tile 4 rows x 14
//   cols (PH zero-padded 100->112).  block = 128 (16 rowg x 8 colg),
//   Mtile = 64 rows, grid = 256 CTAs.  w loaded once per (gene, colg),
//   reused over 4 rows; gl via one LDG.128 per 4 rows (L2-resident).
// =======================================================================
#define TH2    128
#define MT2    64
#define PHP    112
#define SMEM2_FLOATS (Gn * PHP + PHP + PHP + 8 * MT2)
#define SMEM2_BYTES  (SMEM2_FLOATS * 4)     // 60160

__global__ void __launch_bounds__(TH2)
stage2_kernel(const float* __restrict__ Wp1,
              const float* __restrict__ bp1,
              const float* __restrict__ Wp2,
              const float* __restrict__ bp2,
              float* __restrict__ out)
{
    extern __shared__ float sm[];
    float* wp   = sm;                    // [G][PHP], zero-padded
    float* bp1p = sm + Gn * PHP;         // [PHP]
    float* wp2p = bp1p + PHP;            // [PHP]
    float* part = wp2p + PHP;            // [8][MT2]

    const int tid = threadIdx.x;

    for (int i = tid; i < Gn * PHP; i += TH2) {
        int gg = i / PHP, c = i - gg * PHP;
        wp[i] = (c < PHn) ? Wp1[gg * PHn + c] : 0.f;
    }
    if (tid < PHP) {
        bp1p[tid] = (tid < PHn) ? bp1[tid] : 0.f;
        wp2p[tid] = (tid < PHn) ? Wp2[tid] : 0.f;
    }
    __syncthreads();

    const int rowg = tid & 15;          // 16 row-groups of 4 rows
    const int cg   = tid >> 4;          // 8 col-groups of 14 cols
    const int b0   = blockIdx.x * MT2 + rowg * 4;

    // seed accumulators with bias (same bias for all 4 rows)
    ull acc[4][7];
    {
        const ull* bs = reinterpret_cast<const ull*>(bp1p + cg * 14);
#pragma unroll
        for (int q = 0; q < 7; q++) {
            ull v = bs[q];
#pragma unroll
            for (int r = 0; r < 4; r++) acc[r][q] = v;
        }
    }

    const float* glp = g_GL + b0;

#pragma unroll 1
    for (int g0 = 0; g0 < Gn; g0 += 4) {
        float4 gv[4];
#pragma unroll
        for (int j = 0; j < 4; j++)
            gv[j] = *reinterpret_cast<const float4*>(glp + (size_t)(g0 + j) * Bsz);

#pragma unroll
        for (int j = 0; j < 4; j++) {
            const ull* wr = reinterpret_cast<const ull*>(wp + (g0 + j) * PHP + cg * 14);
            ull wv[7];
#pragma unroll
            for (int q = 0; q < 7; q++) wv[q] = wr[q];   // broadcast LDS.64

            float gs[4] = {gv[j].x, gv[j].y, gv[j].z, gv[j].w};
#pragma unroll
            for (int r = 0; r < 4; r++) {
                ull a2 = dup2(gs[r]);
#pragma unroll
                for (int q = 0; q < 7; q++)
                    acc[r][q] = ffma2(a2, wv[q], acc[r][q]);
            }
        }
    }

    // epilogue: relu + dot with Wp2 slice, write partials
    {
        const ull* w2u = reinterpret_cast<const ull*>(wp2p + cg * 14);
        ull w2r[7];
#pragma unroll
        for (int q = 0; q < 7; q++) w2r[q] = w2u[q];
#pragma unroll
        for (int r = 0; r < 4; r++) {
            float y = 0.f;
#pragma unroll
            for (int q = 0; q < 7; q++) {
                float l, h, wl, wh;
                unpack2(acc[r][q], l, h);
                unpack2(w2r[q], wl, wh);
                y += fmaxf(l, 0.f) * wl + fmaxf(h, 0.f) * wh;
            }
            part[cg * MT2 + rowg * 4 + r] = y;
        }
    }
    __syncthreads();

    if (tid < MT2) {
        float s = bp2[0];
#pragma unroll
        for (int c = 0; c < 8; c++) s += part[c * MT2 + tid];
        out[blockIdx.x * MT2 + tid] = s;
    }
}

// =======================================================================
extern "C" void kernel_launch(void* const* d_in, const int* in_sizes, int n_in,
                              void* d_out, int out_size)
{
    const float* x   = (const float*)d_in[0];
    const float* W1  = (const float*)d_in[1];
    const float* b1  = (const float*)d_in[2];
    const float* W2  = (const float*)d_in[3];
    const float* b2  = (const float*)d_in[4];
    const float* Wp1 = (const float*)d_in[5];
    const float* bp1 = (const float*)d_in[6];
    const float* Wp2 = (const float*)d_in[7];
    const float* bp2 = (const float*)d_in[8];
    float* out = (float*)d_out;

    cudaFuncSetAttribute(stage2_kernel,
                         cudaFuncAttributeMaxDynamicSharedMemorySize, SMEM2_BYTES);

    dim3 grid1(Gn, Bsz / ROWS1);
    stage1_kernel<<<grid1, TH1>>>(x, W1, b1, W2, b2);
    stage2_kernel<<<Bsz / MT2, TH2, SMEM2_BYTES>>>(Wp1, bp1, Wp2, bp2, out);
}